// round 2
// baseline (speedup 1.0000x reference)
#include <cuda_runtime.h>
#include <math.h>

#define ENT   9
#define INNER 64
#define BB    16
#define SS    512
#define HH    768
#define ND    (ENT * INNER * 2)   // 1152
#define NEG_INF_F 1000000000000.0f

// Scratch for roped Q/K in [B, ENT, S, INNER] layout (contiguous per (b,h))
__device__ float g_q[BB * ENT * SS * INNER];
__device__ float g_k[BB * ENT * SS * INNER];

// ---------------------------------------------------------------------------
// Kernel A: proj = X @ W + b, reshape (B,S,9,128), split q/k, interleaved RoPE,
// store to g_q / g_k in [B,9,S,64].
// Tiles: 64x64 output, K-tile 16, 256 threads, 4x4 microtile.
// Block column range (64 wide, 128 per head) is entirely q-side or k-side.
// ---------------------------------------------------------------------------
__global__ __launch_bounds__(256) void proj_rope_kernel(
    const float* __restrict__ X,      // [8192, 768]
    const float* __restrict__ W,      // [768, 1152]
    const float* __restrict__ bias)   // [1152]
{
    __shared__ float As[64][17];
    __shared__ float Bs[16][65];

    const int tid = threadIdx.x;
    const int tx = tid & 15;
    const int ty = tid >> 4;
    const int m0 = blockIdx.y * 64;
    const int n0 = blockIdx.x * 64;

    float acc[4][4];
    #pragma unroll
    for (int i = 0; i < 4; i++)
        #pragma unroll
        for (int j = 0; j < 4; j++) acc[i][j] = 0.f;

    for (int k0 = 0; k0 < HH; k0 += 16) {
        #pragma unroll
        for (int i = 0; i < 4; i++) {
            int idx = tid + i * 256;
            int r = idx >> 4, c = idx & 15;
            As[r][c] = X[(m0 + r) * HH + k0 + c];
        }
        #pragma unroll
        for (int i = 0; i < 4; i++) {
            int idx = tid + i * 256;
            int r = idx >> 6, c = idx & 63;
            Bs[r][c] = W[(k0 + r) * ND + n0 + c];
        }
        __syncthreads();
        #pragma unroll
        for (int kk = 0; kk < 16; kk++) {
            float a[4], bfr[4];
            #pragma unroll
            for (int i = 0; i < 4; i++) a[i] = As[ty * 4 + i][kk];
            #pragma unroll
            for (int j = 0; j < 4; j++) bfr[j] = Bs[kk][tx * 4 + j];
            #pragma unroll
            for (int i = 0; i < 4; i++)
                #pragma unroll
                for (int j = 0; j < 4; j++)
                    acc[i][j] = fmaf(a[i], bfr[j], acc[i][j]);
        }
        __syncthreads();
    }

    // Epilogue: bias + interleaved RoPE, scatter to g_q / g_k.
    const int ncol0 = n0 + tx * 4;
    const int head  = ncol0 / 128;
    const int w0    = ncol0 & 127;           // within-head offset of first col
    const bool is_q = (w0 < 64);
    const int d0    = is_q ? w0 : (w0 - 64); // dim within 64 (even, multiple of 4)
    float* dst = is_q ? g_q : g_k;

    #pragma unroll
    for (int i = 0; i < 4; i++) {
        const int m = m0 + ty * 4 + i;
        const int b = m >> 9;       // / 512
        const int s = m & 511;
        #pragma unroll
        for (int p = 0; p < 2; p++) {
            const int d  = d0 + 2 * p;
            const int pi = d >> 1;
            const float v0 = acc[i][2 * p]     + bias[ncol0 + 2 * p];
            const float v1 = acc[i][2 * p + 1] + bias[ncol0 + 2 * p + 1];
            // freq = 10000^(-2*pi/64) = 2^(-pi * log2(10000)/32)
            const float freq = exp2f(-0.41524101186092f * (float)pi);
            float sn, cs;
            sincosf((float)s * freq, &sn, &cs);
            const float o0 = v0 * cs - v1 * sn;
            const float o1 = v1 * cs + v0 * sn;
            const int base = (((b * ENT + head) * SS) + s) * INNER + d;
            dst[base]     = o0;
            dst[base + 1] = o1;
        }
    }
}

// ---------------------------------------------------------------------------
// Kernel B: per (b,h): logits[m,n] = sum_d Q[m,d]*K[n,d], then
// v = logit*pad[n] - (1-pad[n])*NEG_INF; if (m>n) v -= NEG_INF; out = v/8.
// 64x64 tile over K=64, 256 threads, 4x4 microtile, float4 stores.
// ---------------------------------------------------------------------------
__global__ __launch_bounds__(256) void qk_kernel(
    const float* __restrict__ mask,   // [16, 512]
    float* __restrict__ out)          // [16, 9, 512, 512]
{
    const int bz = blockIdx.z;        // b*9 + h
    const int b  = bz / ENT;
    const int m0 = blockIdx.y * 64;
    const int n0 = blockIdx.x * 64;

    __shared__ float Qs[64][65];      // [m][d]
    __shared__ float Ks[64][65];      // [d][n] (transposed on load)

    const int tid = threadIdx.x;
    const int tx = tid & 15;
    const int ty = tid >> 4;

    const float* Qb = g_q + (size_t)bz * SS * INNER;
    const float* Kb = g_k + (size_t)bz * SS * INNER;

    for (int idx = tid; idx < 64 * 64; idx += 256) {
        int r = idx >> 6, c = idx & 63;
        Qs[r][c] = Qb[(m0 + r) * INNER + c];
        Ks[c][r] = Kb[(n0 + r) * INNER + c];
    }
    __syncthreads();

    float acc[4][4];
    #pragma unroll
    for (int i = 0; i < 4; i++)
        #pragma unroll
        for (int j = 0; j < 4; j++) acc[i][j] = 0.f;

    #pragma unroll 16
    for (int kk = 0; kk < 64; kk++) {
        float a[4], bfr[4];
        #pragma unroll
        for (int i = 0; i < 4; i++) a[i] = Qs[ty * 4 + i][kk];
        #pragma unroll
        for (int j = 0; j < 4; j++) bfr[j] = Ks[kk][tx * 4 + j];
        #pragma unroll
        for (int i = 0; i < 4; i++)
            #pragma unroll
            for (int j = 0; j < 4; j++)
                acc[i][j] = fmaf(a[i], bfr[j], acc[i][j]);
    }

    float pads[4];
    #pragma unroll
    for (int j = 0; j < 4; j++) pads[j] = mask[b * SS + n0 + tx * 4 + j];

    #pragma unroll
    for (int i = 0; i < 4; i++) {
        const int m = m0 + ty * 4 + i;
        float4 v;
        float tmp[4];
        #pragma unroll
        for (int j = 0; j < 4; j++) {
            const int n = n0 + tx * 4 + j;
            float val = acc[i][j] * pads[j] - (1.0f - pads[j]) * NEG_INF_F;
            if (m > n) val -= NEG_INF_F;
            tmp[j] = val * 0.125f;   // / sqrt(64)
        }
        v.x = tmp[0]; v.y = tmp[1]; v.z = tmp[2]; v.w = tmp[3];
        *reinterpret_cast<float4*>(
            &out[((size_t)bz * SS + m) * SS + n0 + tx * 4]) = v;
    }
}

extern "C" void kernel_launch(void* const* d_in, const int* in_sizes, int n_in,
                              void* d_out, int out_size) {
    const float* X    = (const float*)d_in[0];  // [16,512,768]
    const float* msk  = (const float*)d_in[1];  // [16,512]
    const float* W    = (const float*)d_in[2];  // [768,1152]
    const float* bias = (const float*)d_in[3];  // [1152]
    float* out = (float*)d_out;                 // [16,9,512,512]

    dim3 gridA(ND / 64, (BB * SS) / 64);        // (18, 128)
    proj_rope_kernel<<<gridA, 256>>>(X, W, bias);

    dim3 gridB(SS / 64, SS / 64, BB * ENT);     // (8, 8, 144)
    qk_kernel<<<gridB, 256>>>(msk, out);
}

// round 3
// speedup vs baseline: 1.3749x; 1.3749x over previous
#include <cuda_runtime.h>
#include <math.h>

#define ENT   9
#define INNER 64
#define BB    16
#define SS    512
#define HH    768
#define ND    (ENT * INNER * 2)   // 1152
#define NEG_INF_F 1000000000000.0f

typedef unsigned long long u64;

__device__ __forceinline__ u64 pack2(float x, float y) {
    u64 r; asm("mov.b64 %0, {%1, %2};" : "=l"(r) : "f"(x), "f"(y)); return r;
}
__device__ __forceinline__ u64 bcast2(float x) {
    u64 r; asm("mov.b64 %0, {%1, %1};" : "=l"(r) : "f"(x)); return r;
}
__device__ __forceinline__ void ffma2(u64 &d, u64 a, u64 b) {
    asm("fma.rn.f32x2 %0, %1, %2, %0;" : "+l"(d) : "l"(a), "l"(b));
}
__device__ __forceinline__ float2 unpack2(u64 v) {
    float2 f; asm("mov.b64 {%0, %1}, %2;" : "=f"(f.x), "=f"(f.y) : "l"(v)); return f;
}

// Scratch for roped Q/K in [B, ENT, S, INNER] layout (contiguous per (b,h))
__device__ float g_q[BB * ENT * SS * INNER];
__device__ float g_k[BB * ENT * SS * INNER];

// ---------------------------------------------------------------------------
// Kernel A: proj = X @ W + b, interleaved RoPE, scatter to g_q / g_k.
// 128x128 tile, Ktile=16, 256 threads, 8x8 microtile on packed f32x2 FMA.
// ---------------------------------------------------------------------------
__global__ __launch_bounds__(256) void proj_rope_kernel(
    const float* __restrict__ X,      // [8192, 768]
    const float* __restrict__ W,      // [768, 1152]
    const float* __restrict__ bias)   // [1152]
{
    __shared__ float At[16][128];     // [k][m]  (transposed A tile)
    __shared__ float Bs[16][128];     // [k][n]

    const int tid = threadIdx.x;
    const int tx  = tid & 15;
    const int ty  = tid >> 4;
    const int m0  = blockIdx.y * 128;
    const int n0  = blockIdx.x * 128;

    u64 acc[8][4];
    #pragma unroll
    for (int i = 0; i < 8; i++)
        #pragma unroll
        for (int j = 0; j < 4; j++) acc[i][j] = 0ull;

    // prefetch tile 0
    float4 ra[2], rb[2];
    #pragma unroll
    for (int i = 0; i < 2; i++) {
        int v = tid + i * 256;                 // 0..511
        int am = v >> 2, ac = (v & 3) * 4;     // A: 128 rows x 16 cols
        ra[i] = *reinterpret_cast<const float4*>(&X[(m0 + am) * HH + ac]);
        int br = v >> 5, bc = (v & 31) * 4;    // B: 16 rows x 128 cols
        rb[i] = *reinterpret_cast<const float4*>(&W[br * ND + n0 + bc]);
    }

    for (int t = 0; t < HH / 16; t++) {
        // store staged regs to smem (A transposed)
        #pragma unroll
        for (int i = 0; i < 2; i++) {
            int v = tid + i * 256;
            int am = v >> 2, ac = (v & 3) * 4;
            At[ac + 0][am] = ra[i].x;
            At[ac + 1][am] = ra[i].y;
            At[ac + 2][am] = ra[i].z;
            At[ac + 3][am] = ra[i].w;
            int br = v >> 5, bc = (v & 31) * 4;
            *reinterpret_cast<float4*>(&Bs[br][bc]) = rb[i];
        }
        __syncthreads();

        // prefetch next tile while computing this one
        if (t < HH / 16 - 1) {
            const int k0 = (t + 1) * 16;
            #pragma unroll
            for (int i = 0; i < 2; i++) {
                int v = tid + i * 256;
                int am = v >> 2, ac = (v & 3) * 4;
                ra[i] = *reinterpret_cast<const float4*>(&X[(m0 + am) * HH + k0 + ac]);
                int br = v >> 5, bc = (v & 31) * 4;
                rb[i] = *reinterpret_cast<const float4*>(&W[(k0 + br) * ND + n0 + bc]);
            }
        }

        #pragma unroll
        for (int kk = 0; kk < 16; kk++) {
            float4 a0 = *reinterpret_cast<const float4*>(&At[kk][ty * 8]);
            float4 a1 = *reinterpret_cast<const float4*>(&At[kk][ty * 8 + 4]);
            float4 b0 = *reinterpret_cast<const float4*>(&Bs[kk][tx * 8]);
            float4 b1 = *reinterpret_cast<const float4*>(&Bs[kk][tx * 8 + 4]);
            u64 ap[8], bp[4];
            ap[0] = bcast2(a0.x); ap[1] = bcast2(a0.y);
            ap[2] = bcast2(a0.z); ap[3] = bcast2(a0.w);
            ap[4] = bcast2(a1.x); ap[5] = bcast2(a1.y);
            ap[6] = bcast2(a1.z); ap[7] = bcast2(a1.w);
            bp[0] = pack2(b0.x, b0.y); bp[1] = pack2(b0.z, b0.w);
            bp[2] = pack2(b1.x, b1.y); bp[3] = pack2(b1.z, b1.w);
            #pragma unroll
            for (int i = 0; i < 8; i++)
                #pragma unroll
                for (int j = 0; j < 4; j++)
                    ffma2(acc[i][j], ap[i], bp[j]);
        }
        __syncthreads();
    }

    // Epilogue: bias + interleaved RoPE, scatter to g_q / g_k.
    const int ncol0 = n0 + tx * 8;
    const int head  = ncol0 / 128;
    const int w0    = ncol0 & 127;
    const bool is_q = (w0 < 64);
    const int d0    = is_q ? w0 : (w0 - 64);   // multiple of 8
    float* dst = is_q ? g_q : g_k;

    #pragma unroll
    for (int i = 0; i < 8; i++) {
        const int m = m0 + ty * 8 + i;
        const int b = m >> 9;
        const int s = m & 511;
        #pragma unroll
        for (int p = 0; p < 4; p++) {
            const int d  = d0 + 2 * p;
            const int pi = d >> 1;
            float2 v = unpack2(acc[i][p]);
            const float v0 = v.x + bias[ncol0 + 2 * p];
            const float v1 = v.y + bias[ncol0 + 2 * p + 1];
            const float freq = exp2f(-0.41524101186092f * (float)pi);
            float sn, cs;
            sincosf((float)s * freq, &sn, &cs);
            float2 o;
            o.x = v0 * cs - v1 * sn;
            o.y = v1 * cs + v0 * sn;
            const int base = (((b * ENT + head) * SS) + s) * INNER + d;
            *reinterpret_cast<float2*>(&dst[base]) = o;
        }
    }
}

// ---------------------------------------------------------------------------
// Kernel B: per (b,h): logits = Q K^T, mask + causal + scale.
// 128x128 tile, full K=64 in smem (transposed), 8x8 microtile, f32x2 FMA.
// 64 KB dynamic smem.
// ---------------------------------------------------------------------------
__global__ __launch_bounds__(256) void qk_kernel(
    const float* __restrict__ mask,   // [16, 512]
    float* __restrict__ out)          // [16, 9, 512, 512]
{
    extern __shared__ float sm[];
    float (*Qt)[128] = reinterpret_cast<float(*)[128]>(sm);            // [d][m]
    float (*Kt)[128] = reinterpret_cast<float(*)[128]>(sm + 64 * 128); // [d][n]

    const int bz = blockIdx.z;        // b*9 + h
    const int b  = bz / ENT;
    const int m0 = blockIdx.y * 128;
    const int n0 = blockIdx.x * 128;

    const int tid = threadIdx.x;
    const int tx  = tid & 15;
    const int ty  = tid >> 4;

    const float* Qb = g_q + (size_t)bz * SS * INNER;
    const float* Kb = g_k + (size_t)bz * SS * INNER;

    // stage Q,K tiles transposed: [d][row]
    #pragma unroll
    for (int i = 0; i < 8; i++) {
        int v = tid + i * 256;             // 0..2047
        int r = v >> 4, c4 = (v & 15) * 4; // 128 rows x 64 dims
        float4 q = *reinterpret_cast<const float4*>(&Qb[(m0 + r) * INNER + c4]);
        Qt[c4 + 0][r] = q.x; Qt[c4 + 1][r] = q.y;
        Qt[c4 + 2][r] = q.z; Qt[c4 + 3][r] = q.w;
        float4 k = *reinterpret_cast<const float4*>(&Kb[(n0 + r) * INNER + c4]);
        Kt[c4 + 0][r] = k.x; Kt[c4 + 1][r] = k.y;
        Kt[c4 + 2][r] = k.z; Kt[c4 + 3][r] = k.w;
    }
    __syncthreads();

    u64 acc[8][4];
    #pragma unroll
    for (int i = 0; i < 8; i++)
        #pragma unroll
        for (int j = 0; j < 4; j++) acc[i][j] = 0ull;

    #pragma unroll 8
    for (int kk = 0; kk < 64; kk++) {
        float4 a0 = *reinterpret_cast<const float4*>(&Qt[kk][ty * 8]);
        float4 a1 = *reinterpret_cast<const float4*>(&Qt[kk][ty * 8 + 4]);
        float4 b0 = *reinterpret_cast<const float4*>(&Kt[kk][tx * 8]);
        float4 b1 = *reinterpret_cast<const float4*>(&Kt[kk][tx * 8 + 4]);
        u64 ap[8], bp[4];
        ap[0] = bcast2(a0.x); ap[1] = bcast2(a0.y);
        ap[2] = bcast2(a0.z); ap[3] = bcast2(a0.w);
        ap[4] = bcast2(a1.x); ap[5] = bcast2(a1.y);
        ap[6] = bcast2(a1.z); ap[7] = bcast2(a1.w);
        bp[0] = pack2(b0.x, b0.y); bp[1] = pack2(b0.z, b0.w);
        bp[2] = pack2(b1.x, b1.y); bp[3] = pack2(b1.z, b1.w);
        #pragma unroll
        for (int i = 0; i < 8; i++)
            #pragma unroll
            for (int j = 0; j < 4; j++)
                ffma2(acc[i][j], ap[i], bp[j]);
    }

    float pads[8];
    #pragma unroll
    for (int j = 0; j < 8; j++) pads[j] = mask[b * SS + n0 + tx * 8 + j];

    #pragma unroll
    for (int i = 0; i < 8; i++) {
        const int m = m0 + ty * 8 + i;
        float tmp[8];
        #pragma unroll
        for (int j = 0; j < 4; j++) {
            float2 v = unpack2(acc[i][j]);
            const int n_lo = n0 + tx * 8 + 2 * j;
            float lo = v.x * pads[2 * j]     - (1.0f - pads[2 * j])     * NEG_INF_F;
            float hi = v.y * pads[2 * j + 1] - (1.0f - pads[2 * j + 1]) * NEG_INF_F;
            if (m > n_lo)     lo -= NEG_INF_F;
            if (m > n_lo + 1) hi -= NEG_INF_F;
            tmp[2 * j]     = lo * 0.125f;
            tmp[2 * j + 1] = hi * 0.125f;
        }
        float4 v0 = make_float4(tmp[0], tmp[1], tmp[2], tmp[3]);
        float4 v1 = make_float4(tmp[4], tmp[5], tmp[6], tmp[7]);
        float* base = &out[((size_t)bz * SS + m) * SS + n0 + tx * 8];
        *reinterpret_cast<float4*>(base)     = v0;
        *reinterpret_cast<float4*>(base + 4) = v1;
    }
}

extern "C" void kernel_launch(void* const* d_in, const int* in_sizes, int n_in,
                              void* d_out, int out_size) {
    const float* X    = (const float*)d_in[0];  // [16,512,768]
    const float* msk  = (const float*)d_in[1];  // [16,512]
    const float* W    = (const float*)d_in[2];  // [768,1152]
    const float* bias = (const float*)d_in[3];  // [1152]
    float* out = (float*)d_out;                 // [16,9,512,512]

    dim3 gridA(ND / 128, (BB * SS) / 128);      // (9, 64)
    proj_rope_kernel<<<gridA, 256>>>(X, W, bias);

    cudaFuncSetAttribute(qk_kernel, cudaFuncAttributeMaxDynamicSharedMemorySize, 65536);
    dim3 gridB(SS / 128, SS / 128, BB * ENT);   // (4, 4, 144)
    qk_kernel<<<gridB, 256, 65536>>>(msk, out);
}